// round 17
// baseline (speedup 1.0000x reference)
#include <cuda_runtime.h>
#include <math.h>
#include <stdint.h>

#define Sq  2048
#define Dd  512
#define Hh  8
#define DHh 64
#define CWw 128
#define NSPLIT 4
#define KSPL (Dd / NSPLIT)    // 128

// ---------------- scratch (device globals) -------------------------------------
__device__ float g_cur[Sq * Dd];
__device__ float g_q[Sq * DHh];
__device__ float g_k[Sq * DHh];
__device__ float g_v[Sq * DHh];
__device__ float g_part[3][NSPLIT][Sq * DHh];
__device__ float g_pm[2][Sq];
__device__ float g_ps[2][Sq];
__device__ float g_pv[2][Sq * DHh];
__device__ float g_wvu_hi[Hh * Dd * DHh];    // pre-split Wvu (1MB each)
__device__ float g_wvu_lo[Hh * Dd * DHh];

// ---------------- tf32 helpers ----------------------------------------------------
__device__ __forceinline__ void tf32_split(float x, float& hi, float& lo) {
    asm("cvt.rna.tf32.f32 %0, %1;" : "=f"(hi) : "f"(x));
    float l = x - hi;
    asm("cvt.rna.tf32.f32 %0, %1;" : "=f"(lo) : "f"(l));
}
__device__ __forceinline__ void split4(float4 v, float4& hi, float4& lo) {
    tf32_split(v.x, hi.x, lo.x);
    tf32_split(v.y, hi.y, lo.y);
    tf32_split(v.z, hi.z, lo.z);
    tf32_split(v.w, hi.w, lo.w);
}
__device__ __forceinline__ uint32_t fu(float f) { return __float_as_uint(f); }

__device__ __forceinline__ void mma_tf32(float* c, uint32_t a0, uint32_t a1,
                                         uint32_t a2, uint32_t a3,
                                         uint32_t b0, uint32_t b1) {
    asm volatile(
        "mma.sync.aligned.m16n8k8.row.col.f32.tf32.tf32.f32 "
        "{%0,%1,%2,%3}, {%4,%5,%6,%7}, {%8,%9}, {%0,%1,%2,%3};"
        : "+f"(c[0]), "+f"(c[1]), "+f"(c[2]), "+f"(c[3])
        : "r"(a0), "r"(a1), "r"(a2), "r"(a3), "r"(b0), "r"(b1));
}

// ---------------- init: cur = x -------------------------------------------------
__global__ void init_kernel(const float4* __restrict__ x) {
    int i = blockIdx.x * blockDim.x + threadIdx.x;
    ((float4*)g_cur)[i] = x[i];
}

// ---------------- one-shot Wvu hi/lo pre-split (runs once per replay) -----------
__global__ void wsplit_kernel(const float* __restrict__ Wvu) {
    int i = blockIdx.x * blockDim.x + threadIdx.x;  // float4 index
    float4 v = ((const float4*)Wvu)[i];
    float4 hi, lo;
    split4(v, hi, lo);
    ((float4*)g_wvu_hi)[i] = hi;
    ((float4*)g_wvu_lo)[i] = lo;
}

// ---------------- qkv split-K partial GEMM via tf32x3 tensor cores (R16 WIN) ----
__global__ __launch_bounds__(128) void qkv_partial(const float* __restrict__ Wq,
                                                   const float* __restrict__ Wk,
                                                   const float* __restrict__ Wvd, int h)
{
    __shared__ float Ah[32 * 36], Al[32 * 36];
    __shared__ float Bh[64 * 36], Bl[64 * 36];

    const int sel = blockIdx.y;
    const int sp  = blockIdx.z;
    const float* B = (sel == 0 ? Wq : sel == 1 ? Wk : Wvd) + (size_t)h * DHh * Dd;
    float* C = &g_part[sel][sp][0];
    const int m0 = blockIdx.x * 32;
    const int kb = sp * KSPL;

    const int t    = threadIdx.x;
    const int w    = t >> 5;
    const int lane = t & 31;
    const int g    = lane >> 2;
    const int tg   = lane & 3;
    const int mw   = (w & 1) * 16;
    const int nw   = (w >> 1) * 32;

    float c[4][4] = {};

    for (int k0 = kb; k0 < kb + KSPL; k0 += 32) {
        #pragma unroll
        for (int r = 0; r < 2; r++) {
            int f = t + r * 128;
            int m = f >> 3, kv = f & 7;
            float4 va = *(const float4*)&g_cur[(size_t)(m0 + m) * Dd + k0 + kv * 4];
            float4 hi, lo;
            split4(va, hi, lo);
            *(float4*)&Ah[m * 36 + kv * 4] = hi;
            *(float4*)&Al[m * 36 + kv * 4] = lo;
        }
        #pragma unroll
        for (int r = 0; r < 4; r++) {
            int f = t + r * 128;
            int n = f >> 3, kv = f & 7;
            float4 vb = *(const float4*)&B[(size_t)n * Dd + k0 + kv * 4];
            float4 hi, lo;
            split4(vb, hi, lo);
            *(float4*)&Bh[n * 36 + kv * 4] = hi;
            *(float4*)&Bl[n * 36 + kv * 4] = lo;
        }
        __syncthreads();

        #pragma unroll
        for (int kk = 0; kk < 32; kk += 8) {
            uint32_t a0h = fu(Ah[(mw + g)     * 36 + kk + tg]);
            uint32_t a1h = fu(Ah[(mw + g + 8) * 36 + kk + tg]);
            uint32_t a2h = fu(Ah[(mw + g)     * 36 + kk + tg + 4]);
            uint32_t a3h = fu(Ah[(mw + g + 8) * 36 + kk + tg + 4]);
            uint32_t a0l = fu(Al[(mw + g)     * 36 + kk + tg]);
            uint32_t a1l = fu(Al[(mw + g + 8) * 36 + kk + tg]);
            uint32_t a2l = fu(Al[(mw + g)     * 36 + kk + tg + 4]);
            uint32_t a3l = fu(Al[(mw + g + 8) * 36 + kk + tg + 4]);
            #pragma unroll
            for (int i = 0; i < 4; i++) {
                int n0 = nw + 8 * i;
                uint32_t b0h = fu(Bh[(n0 + g) * 36 + kk + tg]);
                uint32_t b1h = fu(Bh[(n0 + g) * 36 + kk + tg + 4]);
                uint32_t b0l = fu(Bl[(n0 + g) * 36 + kk + tg]);
                uint32_t b1l = fu(Bl[(n0 + g) * 36 + kk + tg + 4]);
                mma_tf32(c[i], a0h, a1h, a2h, a3h, b0h, b1h);
                mma_tf32(c[i], a0h, a1h, a2h, a3h, b0l, b1l);
                mma_tf32(c[i], a0l, a1l, a2l, a3l, b0h, b1h);
            }
        }
        __syncthreads();
    }

    #pragma unroll
    for (int i = 0; i < 4; i++) {
        int n0 = nw + 8 * i;
        int mA = m0 + mw + g;
        *(float2*)&C[(size_t)mA * DHh + n0 + 2 * tg]       = make_float2(c[i][0], c[i][1]);
        *(float2*)&C[(size_t)(mA + 8) * DHh + n0 + 2 * tg] = make_float2(c[i][2], c[i][3]);
    }
}

__global__ void qkv_reduce()
{
    const int sel = blockIdx.y;
    const int i = blockIdx.x * 256 + threadIdx.x;
    float4 a = ((const float4*)&g_part[sel][0][0])[i];
    float4 b = ((const float4*)&g_part[sel][1][0])[i];
    float4 c = ((const float4*)&g_part[sel][2][0])[i];
    float4 d = ((const float4*)&g_part[sel][3][0])[i];
    float4 o;
    o.x = (a.x + b.x) + (c.x + d.x);
    o.y = (a.y + b.y) + (c.y + d.y);
    o.z = (a.z + b.z) + (c.z + d.z);
    o.w = (a.w + b.w) + (c.w + d.w);
    float* out = (sel == 0 ? g_q : sel == 1 ? g_k : g_v);
    ((float4*)out)[i] = o;
}

// ---------------- attention, window-split halves (R14 proven, verbatim) ---------
#define HT   16
#define KH   144
#define KHP  68
#define PP2  148

#define ASM_K  0
#define ASM_P  (KH * KHP)            // 9792
#define ASM_Q  (ASM_P + HT * PP2)    // +2368
#define ASM_T  (ASM_Q + HT * DHh)    // 13184 floats = 52736 B

__global__ __launch_bounds__(256) void attn_half()
{
    extern __shared__ float sm[];
    float* Ks = sm + ASM_K;
    float* Ps = sm + ASM_P;
    float* Qs = sm + ASM_Q;
    float* Rs = sm + ASM_K;

    const int t    = threadIdx.x;
    const int w    = t >> 5;
    const int lane = t & 31;
    const int j0   = blockIdx.x * HT;
    const int hf   = blockIdx.y;
    const int kstart = j0 - CWw + 128 * hf;

    for (int f = t; f < KH * 16; f += 256) {
        int kk = f >> 4, d4 = f & 15;
        int gk = kstart + kk;
        float4 kv = make_float4(0.f, 0.f, 0.f, 0.f);
        if (gk >= 0 && gk < Sq) kv = ((const float4*)&g_k[(size_t)gk * DHh])[d4];
        *(float4*)&Ks[kk * KHP + d4 * 4] = kv;
    }
    {
        int q = t >> 4, d4 = t & 15;
        ((float4*)&Qs[q * DHh])[d4] = ((const float4*)&g_q[(size_t)(j0 + q) * DHh])[d4];
    }
    __syncthreads();

    const int q0 = 2 * w, q1 = 2 * w + 1;
    {
        float a0[5] = {}, a1[5] = {};
        #pragma unroll
        for (int d4 = 0; d4 < 16; d4++) {
            float4 qa = *(const float4*)&Qs[q0 * DHh + d4 * 4];
            float4 qb = *(const float4*)&Qs[q1 * DHh + d4 * 4];
            #pragma unroll
            for (int jj = 0; jj < 5; jj++) {
                int kk = lane + 32 * jj;
                int kks = kk < KH - 1 ? kk : KH - 1;
                const float4 kv = *(const float4*)&Ks[kks * KHP + d4 * 4];
                a0[jj] = fmaf(kv.x, qa.x, fmaf(kv.y, qa.y, fmaf(kv.z, qa.z, fmaf(kv.w, qa.w, a0[jj]))));
                a1[jj] = fmaf(kv.x, qb.x, fmaf(kv.y, qb.y, fmaf(kv.z, qb.z, fmaf(kv.w, qb.w, a1[jj]))));
            }
        }
        float m0 = -1e30f, m1 = -1e30f;
        #pragma unroll
        for (int jj = 0; jj < 5; jj++) {
            int kk = lane + 32 * jj;
            int gk = kstart + kk;
            bool gok = (gk >= 0) && (gk < Sq);
            bool v0 = gok && (kk >= q0) && (kk < q0 + 128);
            bool v1 = gok && (kk >= q1) && (kk < q1 + 128);
            a0[jj] = v0 ? a0[jj] * 0.125f : -1e30f;
            a1[jj] = v1 ? a1[jj] * 0.125f : -1e30f;
            m0 = fmaxf(m0, a0[jj]);
            m1 = fmaxf(m1, a1[jj]);
        }
        #pragma unroll
        for (int o = 16; o; o >>= 1) {
            m0 = fmaxf(m0, __shfl_xor_sync(0xffffffffu, m0, o));
            m1 = fmaxf(m1, __shfl_xor_sync(0xffffffffu, m1, o));
        }
        float s0 = 0.f, s1 = 0.f;
        #pragma unroll
        for (int jj = 0; jj < 5; jj++) {
            int kk = lane + 32 * jj;
            float e0 = __expf(a0[jj] - m0);
            float e1 = __expf(a1[jj] - m1);
            s0 += e0;
            s1 += e1;
            if (kk < KH) {
                Ps[q0 * PP2 + kk] = e0;
                Ps[q1 * PP2 + kk] = e1;
            }
        }
        #pragma unroll
        for (int o = 16; o; o >>= 1) {
            s0 += __shfl_xor_sync(0xffffffffu, s0, o);
            s1 += __shfl_xor_sync(0xffffffffu, s1, o);
        }
        if (lane == 0) {
            g_pm[hf][j0 + q0] = m0;
            g_pm[hf][j0 + q1] = m1;
            g_ps[hf][j0 + q0] = s0;
            g_ps[hf][j0 + q1] = s1;
        }
    }
    __syncthreads();

    {
        const int qh = (lane >> 4) * 8;
        const int d4 = lane & 15;
        float4 r[8] = {};
        #pragma unroll
        for (int i = 0; i < 18; i++) {
            int kk = w * 18 + i;
            int gk = kstart + kk;
            float4 v4 = make_float4(0.f, 0.f, 0.f, 0.f);
            if (gk >= 0 && gk < Sq)
                v4 = ((const float4*)&g_v[(size_t)gk * DHh])[d4];
            #pragma unroll
            for (int qi = 0; qi < 8; qi++) {
                float p = Ps[(qh + qi) * PP2 + kk];
                r[qi].x = fmaf(p, v4.x, r[qi].x);
                r[qi].y = fmaf(p, v4.y, r[qi].y);
                r[qi].z = fmaf(p, v4.z, r[qi].z);
                r[qi].w = fmaf(p, v4.w, r[qi].w);
            }
        }
        #pragma unroll
        for (int qi = 0; qi < 8; qi++)
            *(float4*)&Rs[(w * HT + qh + qi) * DHh + d4 * 4] = r[qi];
    }
    __syncthreads();

    #pragma unroll
    for (int ii = 0; ii < 4; ii++) {
        int idx = t + 256 * ii;
        int q = idx >> 6, d = idx & 63;
        float s = 0.f;
        #pragma unroll
        for (int ww = 0; ww < 8; ww++) s += Rs[(ww * HT + q) * DHh + d];
        g_pv[hf][(size_t)(j0 + q) * DHh + d] = s;
    }
}

// ---------------- fused combine + up-proj (tf32x3 MMA) + residual + renorm ------
// 16 tokens/block, 256 threads = 8 warps. W staged one 256-row n-half at a time.
#define WPm 68

#define USM_WHI 0
#define USM_WLO (256 * WPm)               // 17408
#define USM_AH  (2 * 256 * WPm)           // 34816
#define USM_AL  (USM_AH + 16 * WPm)       // +1088
#define USM_RS  (USM_AL + 16 * WPm)       // 36992
#define USM_RQ  (USM_RS + 128)
#define USM_TOT (USM_RQ + 128)            // 37248 floats = 148992 B

__global__ __launch_bounds__(256) void upnorm_kernel(int h, int last,
                                                     float* __restrict__ out)
{
    extern __shared__ float sm[];
    float* Whi = sm + USM_WHI;
    float* Wlo = sm + USM_WLO;
    float* Ah  = sm + USM_AH;
    float* Al  = sm + USM_AL;
    float* RedS = sm + USM_RS;
    float* RedQ = sm + USM_RQ;

    const int t    = threadIdx.x;    // 256
    const int w    = t >> 5;         // 0..7
    const int lane = t & 31;
    const int g    = lane >> 2;      // 0..7
    const int tg   = lane & 3;       // 0..3
    const int m0   = blockIdx.x * 16;
    const float* WgHi = g_wvu_hi + (size_t)h * Dd * DHh;
    const float* WgLo = g_wvu_lo + (size_t)h * Dd * DHh;

    // ---- combine 2 softmax halves -> tf32-split into Ah/Al (16 x 64)
    #pragma unroll
    for (int ii = 0; ii < 4; ii++) {
        int idx = t + 256 * ii;          // 0..1023
        int q = idx >> 6, d = idx & 63;
        int m = m0 + q;
        float ma = g_pm[0][m], mb = g_pm[1][m];
        float M  = fmaxf(ma, mb);
        float ca = __expf(ma - M), cb = __expf(mb - M);
        float denom = ca * g_ps[0][m] + cb * g_ps[1][m];
        float pv = ca * g_pv[0][(size_t)m * DHh + d] + cb * g_pv[1][(size_t)m * DHh + d];
        float val = pv / denom;
        float hi, lo;
        tf32_split(val, hi, lo);
        Ah[q * WPm + d] = hi;
        Al[q * WPm + d] = lo;
    }

    float c[2][4][4] = {};   // [half][ntile][creg]

    for (int half = 0; half < 2; half++) {
        __syncthreads();     // prior MMA reads done before overwrite (and As ready)
        #pragma unroll
        for (int r = 0; r < 16; r++) {
            int f = t + r * 256;
            int row = f >> 4, k4 = f & 15;
            *(float4*)&Whi[row * WPm + k4 * 4] =
                *(const float4*)&WgHi[(size_t)(half * 256 + row) * DHh + k4 * 4];
            *(float4*)&Wlo[row * WPm + k4 * 4] =
                *(const float4*)&WgLo[(size_t)(half * 256 + row) * DHh + k4 * 4];
        }
        __syncthreads();

        #pragma unroll
        for (int ks = 0; ks < 8; ks++) {
            int k = ks * 8;
            uint32_t a0h = fu(Ah[g * WPm + k + tg]);
            uint32_t a1h = fu(Ah[(g + 8) * WPm + k + tg]);
            uint32_t a2h = fu(Ah[g * WPm + k + tg + 4]);
            uint32_t a3h = fu(Ah[(g + 8) * WPm + k + tg + 4]);
            uint32_t a0l = fu(Al[g * WPm + k + tg]);
            uint32_t a1l = fu(Al[(g + 8) * WPm + k + tg]);
            uint32_t a2l = fu(Al[g * WPm + k + tg + 4]);
            uint32_t a3l = fu(Al[(g + 8) * WPm + k + tg + 4]);
            #pragma unroll
            for (int i = 0; i < 4; i++) {
                int n0 = w * 32 + 8 * i;
                uint32_t b0h = fu(Whi[(n0 + g) * WPm + k + tg]);
                uint32_t b1h = fu(Whi[(n0 + g) * WPm + k + tg + 4]);
                uint32_t b0l = fu(Wlo[(n0 + g) * WPm + k + tg]);
                uint32_t b1l = fu(Wlo[(n0 + g) * WPm + k + tg + 4]);
                mma_tf32(c[half][i], a0h, a1h, a2h, a3h, b0h, b1h);
                mma_tf32(c[half][i], a0h, a1h, a2h, a3h, b0l, b1l);
                mma_tf32(c[half][i], a0l, a1l, a2l, a3l, b0h, b1h);
            }
        }
    }

    // ---- y = c + cur; single-pass row sums via quad shuffle + smem exchange
    const int r0 = m0 + g, r1 = m0 + g + 8;
    float y0[16], y1[16], cres0[16], cres1[16];
    float s0 = 0.f, q20 = 0.f, s1 = 0.f, q21 = 0.f;
    #pragma unroll
    for (int half = 0; half < 2; half++)
        #pragma unroll
        for (int i = 0; i < 4; i++)
            #pragma unroll
            for (int jj = 0; jj < 2; jj++) {
                int col = half * 256 + w * 32 + 8 * i + 2 * tg + jj;
                int ci  = half * 8 + i * 2 + jj;
                cres0[ci] = g_cur[(size_t)r0 * Dd + col];
                cres1[ci] = g_cur[(size_t)r1 * Dd + col];
                float a = c[half][i][jj]     + cres0[ci];
                float b = c[half][i][2 + jj] + cres1[ci];
                y0[ci] = a;
                y1[ci] = b;
                s0 += a;  q20 = fmaf(a, a, q20);
                s1 += b;  q21 = fmaf(b, b, q21);
            }
    #pragma unroll
    for (int o = 1; o <= 2; o <<= 1) {
        s0  += __shfl_xor_sync(0xffffffffu, s0, o);
        q20 += __shfl_xor_sync(0xffffffffu, q20, o);
        s1  += __shfl_xor_sync(0xffffffffu, s1, o);
        q21 += __shfl_xor_sync(0xffffffffu, q21, o);
    }
    if (tg == 0) {
        RedS[w * 16 + g]     = s0;
        RedS[w * 16 + g + 8] = s1;
        RedQ[w * 16 + g]     = q20;
        RedQ[w * 16 + g + 8] = q21;
    }
    __syncthreads();

    float st0 = 0.f, qt0 = 0.f, st1 = 0.f, qt1 = 0.f;
    #pragma unroll
    for (int ww = 0; ww < 8; ww++) {
        st0 += RedS[ww * 16 + g];
        qt0 += RedQ[ww * 16 + g];
        st1 += RedS[ww * 16 + g + 8];
        qt1 += RedQ[ww * 16 + g + 8];
    }
    float im0 = 512.f / st0;
    float is0 = rsqrtf((qt0 * im0 * im0 * (1.f / 512.f) * 512.f - 512.f) * (1.f / 511.f));
    float im1 = 512.f / st1;
    float is1 = rsqrtf((qt1 * im1 * im1 - 512.f) * (1.f / 511.f));
    // note: im = 1/m1 directly (512/sum); sd2 = (q2*(1/m1)^2 - 512)/511
    is0 = rsqrtf((qt0 * im0 * im0 - 512.f) * (1.f / 511.f));

    #pragma unroll
    for (int half = 0; half < 2; half++)
        #pragma unroll
        for (int i = 0; i < 4; i++)
            #pragma unroll
            for (int jj = 0; jj < 2; jj++) {
                int col = half * 256 + w * 32 + 8 * i + 2 * tg + jj;
                int ci  = half * 8 + i * 2 + jj;
                float nv0 = cres0[ci] + (y0[ci] * im0 - 1.f) * is0 + 1.f;
                float nv1 = cres1[ci] + (y1[ci] * im1 - 1.f) * is1 + 1.f;
                g_cur[(size_t)r0 * Dd + col] = nv0;
                g_cur[(size_t)r1 * Dd + col] = nv1;
                if (last) {
                    out[(size_t)r0 * Dd + col] = nv0 * 0.125f;
                    out[(size_t)r1 * Dd + col] = nv1 * 0.125f;
                }
            }
}

// ---------------- launch ---------------------------------------------------------
extern "C" void kernel_launch(void* const* d_in, const int* in_sizes, int n_in,
                              void* d_out, int out_size)
{
    const float* x   = (const float*)d_in[0];
    const float* Wq  = (const float*)d_in[1];
    const float* Wk  = (const float*)d_in[2];
    const float* Wvd = (const float*)d_in[3];
    const float* Wvu = (const float*)d_in[4];
    float* out = (float*)d_out;

    const int attn_smem = ASM_T * 4;     // 52736 B
    const int up_smem   = USM_TOT * 4;   // 148992 B
    cudaFuncSetAttribute(attn_half, cudaFuncAttributeMaxDynamicSharedMemorySize, attn_smem);
    cudaFuncSetAttribute(upnorm_kernel, cudaFuncAttributeMaxDynamicSharedMemorySize, up_smem);

    init_kernel<<<(Sq * Dd / 4) / 256, 256>>>((const float4*)x);
    wsplit_kernel<<<(Hh * Dd * DHh / 4) / 256, 256>>>(Wvu);
    for (int h = 0; h < Hh; h++) {
        qkv_partial<<<dim3(Sq / 32, 3, NSPLIT), 128>>>(Wq, Wk, Wvd, h);
        qkv_reduce<<<dim3(Sq * DHh / 4 / 256, 3), 256>>>();
        attn_half<<<dim3(Sq / HT, 2), 256, attn_smem>>>();
        upnorm_kernel<<<Sq / 16, 256, up_smem>>>(h, h == Hh - 1 ? 1 : 0, out);
    }
}